// round 1
// baseline (speedup 1.0000x reference)
#include <cuda_runtime.h>
#include <math.h>

#define CI 256
#define CA 128
#define HP 65536      // h*w
#define JJ 131072     // K*h*w
#define BK 16

// ---------------- scratch (device globals; no runtime allocation) ----------
__device__ __align__(16) float g_theta[(size_t)CA * JJ];   // tmp_theta [c][j]
__device__ __align__(16) float g_pi[(size_t)CA * JJ];      // pi raw, then exp(pi-max)
__device__ __align__(16) float g_rowmax[CA];
__device__ __align__(16) float g_rowsum[CA];
__device__ __align__(16) float g_psum[CA * 64];
__device__ __align__(16) float g_gun[CA * CA];             // unnormalized tmpG
__device__ __align__(16) float g_w2[CI * CA];              // w_out @ tmpG

// ---------------- K1: feats = W[384,256] @ X[256,J]; g-softmax fused -------
__global__ __launch_bounds__(256) void k_feats(
    const float* __restrict__ content, const float* __restrict__ style,
    const float* __restrict__ w_theta, const float* __restrict__ b_theta,
    const float* __restrict__ w_pi,    const float* __restrict__ b_pi,
    const float* __restrict__ w_g,     const float* __restrict__ b_g,
    float* __restrict__ out_dist)
{
    __shared__ float As[128][BK + 1];
    __shared__ float Bs[BK][128];
    __shared__ float part[16][128];
    __shared__ float colred[128];

    const int tid = threadIdx.x;
    const int tx = tid & 15, ty = tid >> 4;
    const int by = blockIdx.y;
    const int j0 = blockIdx.x * 128;
    const int kb = (j0 >= HP) ? 1 : 0;
    const float* X = kb ? style : content;
    const int p0 = j0 - kb * HP;
    const float* W  = (by == 0) ? w_theta : ((by == 1) ? w_pi : w_g);
    const float* Bv = (by == 0) ? b_theta : ((by == 1) ? b_pi : b_g);

    float acc[8][8];
    #pragma unroll
    for (int i = 0; i < 8; i++)
        #pragma unroll
        for (int jq = 0; jq < 8; jq++) acc[i][jq] = 0.f;

    for (int c0 = 0; c0 < CI; c0 += BK) {
        #pragma unroll
        for (int r = 0; r < 2; r++) {
            int idx = tid + r * 256;
            int m = idx >> 2, q = idx & 3;
            float4 v = *reinterpret_cast<const float4*>(&W[m * CI + c0 + q * 4]);
            As[m][q * 4 + 0] = v.x; As[m][q * 4 + 1] = v.y;
            As[m][q * 4 + 2] = v.z; As[m][q * 4 + 3] = v.w;
        }
        #pragma unroll
        for (int r = 0; r < 2; r++) {
            int idx = tid + r * 256;
            int kk = idx >> 5, q = idx & 31;
            float4 v = *reinterpret_cast<const float4*>(
                &X[(size_t)(c0 + kk) * HP + p0 + q * 4]);
            *reinterpret_cast<float4*>(&Bs[kk][q * 4]) = v;
        }
        __syncthreads();
        #pragma unroll
        for (int kk = 0; kk < BK; kk++) {
            float ra[8], rb[8];
            #pragma unroll
            for (int i = 0; i < 8; i++) ra[i] = As[ty * 8 + i][kk];
            #pragma unroll
            for (int jq = 0; jq < 8; jq++) rb[jq] = Bs[kk][tx * 8 + jq];
            #pragma unroll
            for (int i = 0; i < 8; i++)
                #pragma unroll
                for (int jq = 0; jq < 8; jq++)
                    acc[i][jq] += ra[i] * rb[jq];
        }
        __syncthreads();
    }
    #pragma unroll
    for (int i = 0; i < 8; i++) {
        float b = Bv[ty * 8 + i];
        #pragma unroll
        for (int jq = 0; jq < 8; jq++) acc[i][jq] += b;
    }

    if (by < 2) {
        float* dst = (by == 0) ? g_theta : g_pi;
        #pragma unroll
        for (int i = 0; i < 8; i++) {
            int c = ty * 8 + i;
            float* p = &dst[(size_t)c * JJ + j0 + tx * 8];
            *reinterpret_cast<float4*>(p) =
                make_float4(acc[i][0], acc[i][1], acc[i][2], acc[i][3]);
            *reinterpret_cast<float4*>(p + 4) =
                make_float4(acc[i][4], acc[i][5], acc[i][6], acc[i][7]);
        }
    } else {
        // per-pixel softmax over the 128 g-channels (all in this block's tile)
        #pragma unroll
        for (int jq = 0; jq < 8; jq++) {
            float m = acc[0][jq];
            #pragma unroll
            for (int i = 1; i < 8; i++) m = fmaxf(m, acc[i][jq]);
            part[ty][tx * 8 + jq] = m;
        }
        __syncthreads();
        if (tid < 128) {
            float m = part[0][tid];
            #pragma unroll
            for (int t2 = 1; t2 < 16; t2++) m = fmaxf(m, part[t2][tid]);
            colred[tid] = m;
        }
        __syncthreads();
        float cm[8], ps[8];
        #pragma unroll
        for (int jq = 0; jq < 8; jq++) { cm[jq] = colred[tx * 8 + jq]; ps[jq] = 0.f; }
        #pragma unroll
        for (int i = 0; i < 8; i++)
            #pragma unroll
            for (int jq = 0; jq < 8; jq++) {
                float e = __expf(acc[i][jq] - cm[jq]);
                acc[i][jq] = e; ps[jq] += e;
            }
        __syncthreads();
        #pragma unroll
        for (int jq = 0; jq < 8; jq++) part[ty][tx * 8 + jq] = ps[jq];
        __syncthreads();
        if (tid < 128) {
            float s = 0.f;
            #pragma unroll
            for (int t2 = 0; t2 < 16; t2++) s += part[t2][tid];
            colred[tid] = 1.0f / s;
        }
        __syncthreads();
        float inv[8];
        #pragma unroll
        for (int jq = 0; jq < 8; jq++) inv[jq] = colred[tx * 8 + jq];
        #pragma unroll
        for (int i = 0; i < 8; i++) {
            int c = ty * 8 + i;
            float* p = &out_dist[(size_t)c * JJ + j0 + tx * 8];
            *reinterpret_cast<float4*>(p) = make_float4(
                acc[i][0] * inv[0], acc[i][1] * inv[1],
                acc[i][2] * inv[2], acc[i][3] * inv[3]);
            *reinterpret_cast<float4*>(p + 4) = make_float4(
                acc[i][4] * inv[4], acc[i][5] * inv[5],
                acc[i][6] * inv[6], acc[i][7] * inv[7]);
        }
    }
}

// ---------------- K2: per-row max of pi; zero gun ---------------------------
__global__ __launch_bounds__(256) void k_rowmax()
{
    const int c = blockIdx.x;
    const float* row = &g_pi[(size_t)c * JJ];
    float m = -1e30f;
    for (int j = threadIdx.x * 4; j < JJ; j += 1024) {
        float4 v = *reinterpret_cast<const float4*>(&row[j]);
        m = fmaxf(m, fmaxf(fmaxf(v.x, v.y), fmaxf(v.z, v.w)));
    }
    __shared__ float red[256];
    red[threadIdx.x] = m;
    __syncthreads();
    for (int s = 128; s > 0; s >>= 1) {
        if (threadIdx.x < s) red[threadIdx.x] = fmaxf(red[threadIdx.x], red[threadIdx.x + s]);
        __syncthreads();
    }
    if (threadIdx.x == 0) g_rowmax[c] = red[0];
    if (threadIdx.x < 128) g_gun[c * 128 + threadIdx.x] = 0.f;
}

// ---------------- K3: e = exp(pi - max); deterministic partial sums --------
__global__ __launch_bounds__(256) void k_exp()
{
    const int c = blockIdx.y;
    const int base = blockIdx.x * 2048;
    const float rm = g_rowmax[c];
    float* row = &g_pi[(size_t)c * JJ + base];
    float s = 0.f;
    #pragma unroll
    for (int r = 0; r < 2; r++) {
        int off = (threadIdx.x + r * 256) * 4;
        float4 v = *reinterpret_cast<float4*>(&row[off]);
        v.x = __expf(v.x - rm); v.y = __expf(v.y - rm);
        v.z = __expf(v.z - rm); v.w = __expf(v.w - rm);
        s += v.x + v.y + v.z + v.w;
        *reinterpret_cast<float4*>(&row[off]) = v;
    }
    __shared__ float red[256];
    red[threadIdx.x] = s;
    __syncthreads();
    for (int st = 128; st > 0; st >>= 1) {
        if (threadIdx.x < st) red[threadIdx.x] += red[threadIdx.x + st];
        __syncthreads();
    }
    if (threadIdx.x == 0) g_psum[c * 64 + blockIdx.x] = red[0];
}

// ---------------- K4: rowsum = sum of partials ------------------------------
__global__ void k_rowsum()
{
    int c = threadIdx.x;
    float s = 0.f;
    #pragma unroll
    for (int b = 0; b < 64; b++) s += g_psum[c * 64 + b];
    g_rowsum[c] = s;
}

// ---------------- K5: gun[m][n] += sum_j theta[m][j]*e[n][j] (split-K) -----
__global__ __launch_bounds__(256) void k_gun()
{
    __shared__ float Am[128][BK + 1];
    __shared__ float Bn[128][BK + 1];
    const int tid = threadIdx.x, tx = tid & 15, ty = tid >> 4;
    const size_t jb = (size_t)blockIdx.x * 1024;

    float acc[8][8];
    #pragma unroll
    for (int i = 0; i < 8; i++)
        #pragma unroll
        for (int jq = 0; jq < 8; jq++) acc[i][jq] = 0.f;

    for (int jc = 0; jc < 1024; jc += BK) {
        size_t j0 = jb + jc;
        #pragma unroll
        for (int r = 0; r < 2; r++) {
            int idx = tid + r * 256;
            int m = idx >> 2, q = idx & 3;
            float4 va = *reinterpret_cast<const float4*>(&g_theta[(size_t)m * JJ + j0 + q * 4]);
            Am[m][q * 4 + 0] = va.x; Am[m][q * 4 + 1] = va.y;
            Am[m][q * 4 + 2] = va.z; Am[m][q * 4 + 3] = va.w;
            float4 vb = *reinterpret_cast<const float4*>(&g_pi[(size_t)m * JJ + j0 + q * 4]);
            Bn[m][q * 4 + 0] = vb.x; Bn[m][q * 4 + 1] = vb.y;
            Bn[m][q * 4 + 2] = vb.z; Bn[m][q * 4 + 3] = vb.w;
        }
        __syncthreads();
        #pragma unroll
        for (int kk = 0; kk < BK; kk++) {
            float ra[8], rb[8];
            #pragma unroll
            for (int i = 0; i < 8; i++) ra[i] = Am[ty * 8 + i][kk];
            #pragma unroll
            for (int jq = 0; jq < 8; jq++) rb[jq] = Bn[tx * 8 + jq][kk];
            #pragma unroll
            for (int i = 0; i < 8; i++)
                #pragma unroll
                for (int jq = 0; jq < 8; jq++)
                    acc[i][jq] += ra[i] * rb[jq];
        }
        __syncthreads();
    }
    #pragma unroll
    for (int i = 0; i < 8; i++)
        #pragma unroll
        for (int jq = 0; jq < 8; jq++)
            atomicAdd(&g_gun[(ty * 8 + i) * 128 + tx * 8 + jq], acc[i][jq]);
}

// ---------------- K6: W2 = (w_out @ gun) / rowsum ---------------------------
__global__ void k_w2(const float* __restrict__ w_out)
{
    const int o = blockIdx.x;
    const int n = threadIdx.x;
    float s = 0.f;
    #pragma unroll 8
    for (int m = 0; m < CA; m++) s += w_out[o * CA + m] * g_gun[m * CA + n];
    g_w2[o * CA + n] = s / g_rowsum[n];
}

// ---------------- K7: alpha_gathering = transpose(e / rowsum) --------------
__global__ __launch_bounds__(256) void k_gath(float* __restrict__ out_gath)
{
    __shared__ float tile[32][33];
    const int jt = blockIdx.x * 32, ct = blockIdx.y * 32;
    const int tx = threadIdx.x & 31, ty = threadIdx.x >> 5;  // ty < 8
    #pragma unroll
    for (int r = 0; r < 4; r++) {
        int c = ct + ty + r * 8;
        tile[ty + r * 8][tx] = g_pi[(size_t)c * JJ + jt + tx] * (1.0f / g_rowsum[c]);
    }
    __syncthreads();
    #pragma unroll
    for (int r = 0; r < 4; r++) {
        int jl = ty + r * 8;
        out_gath[(size_t)(jt + jl) * CA + ct + tx] = tile[tx][jl];
    }
}

// ---------------- K8: out = W2[256,128] @ softmax_g[128,J] + b_out ---------
__global__ __launch_bounds__(256) void k_out(
    const float* __restrict__ b_out, const float* __restrict__ sg,
    float* __restrict__ out)
{
    __shared__ float As[128][BK + 1];
    __shared__ float Bs[BK][128];
    const int tid = threadIdx.x, tx = tid & 15, ty = tid >> 4;
    const int rb = blockIdx.y * 128;
    const int j0 = blockIdx.x * 128;

    float acc[8][8];
    #pragma unroll
    for (int i = 0; i < 8; i++)
        #pragma unroll
        for (int jq = 0; jq < 8; jq++) acc[i][jq] = 0.f;

    for (int k0 = 0; k0 < CA; k0 += BK) {
        #pragma unroll
        for (int r = 0; r < 2; r++) {
            int idx = tid + r * 256;
            int m = idx >> 2, q = idx & 3;
            float4 v = *reinterpret_cast<const float4*>(&g_w2[(rb + m) * CA + k0 + q * 4]);
            As[m][q * 4 + 0] = v.x; As[m][q * 4 + 1] = v.y;
            As[m][q * 4 + 2] = v.z; As[m][q * 4 + 3] = v.w;
        }
        #pragma unroll
        for (int r = 0; r < 2; r++) {
            int idx = tid + r * 256;
            int kk = idx >> 5, q = idx & 31;
            float4 v = *reinterpret_cast<const float4*>(&sg[(size_t)(k0 + kk) * JJ + j0 + q * 4]);
            *reinterpret_cast<float4*>(&Bs[kk][q * 4]) = v;
        }
        __syncthreads();
        #pragma unroll
        for (int kk = 0; kk < BK; kk++) {
            float ra[8], rb2[8];
            #pragma unroll
            for (int i = 0; i < 8; i++) ra[i] = As[ty * 8 + i][kk];
            #pragma unroll
            for (int jq = 0; jq < 8; jq++) rb2[jq] = Bs[kk][tx * 8 + jq];
            #pragma unroll
            for (int i = 0; i < 8; i++)
                #pragma unroll
                for (int jq = 0; jq < 8; jq++)
                    acc[i][jq] += ra[i] * rb2[jq];
        }
        __syncthreads();
    }

    const int kb = (j0 >= HP) ? 1 : 0;
    const size_t obase = kb ? (size_t)CI * HP : 0;
    const int p0 = j0 - kb * HP;
    #pragma unroll
    for (int i = 0; i < 8; i++) {
        int o = rb + ty * 8 + i;
        float bo = b_out[o];
        float* p = &out[obase + (size_t)o * HP + p0 + tx * 8];
        *reinterpret_cast<float4*>(p) = make_float4(
            acc[i][0] + bo, acc[i][1] + bo, acc[i][2] + bo, acc[i][3] + bo);
        *reinterpret_cast<float4*>(p + 4) = make_float4(
            acc[i][4] + bo, acc[i][5] + bo, acc[i][6] + bo, acc[i][7] + bo);
    }
}

// ---------------- launch -----------------------------------------------------
extern "C" void kernel_launch(void* const* d_in, const int* in_sizes, int n_in,
                              void* d_out, int out_size)
{
    const float* content = (const float*)d_in[0];
    const float* style   = (const float*)d_in[1];
    const float* w_theta = (const float*)d_in[2];
    const float* b_theta = (const float*)d_in[3];
    const float* w_pi    = (const float*)d_in[4];
    const float* b_pi    = (const float*)d_in[5];
    const float* w_g     = (const float*)d_in[6];
    const float* b_g     = (const float*)d_in[7];
    const float* w_out   = (const float*)d_in[8];
    const float* b_out   = (const float*)d_in[9];

    float* out  = (float*)d_out;
    float* gath = out + (size_t)2 * CI * HP;            // alpha_gathering
    float* dist = gath + (size_t)CA * JJ;               // alpha_distribute

    k_feats<<<dim3(JJ / 128, 3), 256>>>(content, style, w_theta, b_theta,
                                        w_pi, b_pi, w_g, b_g, dist);
    k_rowmax<<<128, 256>>>();
    k_exp<<<dim3(64, 128), 256>>>();
    k_rowsum<<<1, 128>>>();
    k_gun<<<128, 256>>>();
    k_w2<<<256, 128>>>(w_out);
    k_gath<<<dim3(JJ / 32, CA / 32), 256>>>(gath);
    k_out<<<dim3(JJ / 128, 2), 256>>>(b_out, dist, out);
}

// round 3
// speedup vs baseline: 2.3009x; 2.3009x over previous
#include <cuda_runtime.h>
#include <stdint.h>
#include <math.h>

#define CI 256
#define CA 128
#define HP 65536      // h*w
#define JJ 131072     // K*h*w
#define NJB 1024      // JJ / 128

#define ASTR 36       // smem stride for [row][k32] tiles (conflict-free frag reads)
#define BSTR 136      // smem stride for [k32][n128] tiles
#define CSTR 132      // smem stride for C staging [128][128]

// ---------------- scratch (device globals) ----------------------------------
__device__ __align__(16) float g_theta[(size_t)CA * JJ];   // theta [c][j]
__device__ __align__(16) float g_pi[(size_t)CA * JJ];      // e = exp(pi) [c][j]
__device__ __align__(16) float g_psum[CA * NJB];           // per-block row sums
__device__ __align__(16) float g_rinv[CA];                 // 1 / rowsum
__device__ __align__(16) float g_gun[CA * CA];             // unnormalized tmpG
__device__ __align__(16) float g_w2[CI * CA];              // w_out @ tmpG (normalized)

extern __shared__ float dynsm[];

// ---------------- tf32 helpers ----------------------------------------------
__device__ __forceinline__ uint32_t f2tf(float f) {
    uint32_t u;
    asm("cvt.rna.tf32.f32 %0, %1;" : "=r"(u) : "f"(f));
    return u;
}
__device__ __forceinline__ uint4 f2tf4(float4 v) {
    return make_uint4(f2tf(v.x), f2tf(v.y), f2tf(v.z), f2tf(v.w));
}
__device__ __forceinline__ void mma8(float* d, const uint32_t* a, const uint32_t* b) {
    asm volatile(
        "mma.sync.aligned.m16n8k8.row.col.f32.tf32.tf32.f32 "
        "{%0,%1,%2,%3}, {%4,%5,%6,%7}, {%8,%9}, {%0,%1,%2,%3};"
        : "+f"(d[0]), "+f"(d[1]), "+f"(d[2]), "+f"(d[3])
        : "r"(a[0]), "r"(a[1]), "r"(a[2]), "r"(a[3]), "r"(b[0]), "r"(b[1]));
}

// ---------------- K1: feats = W[128,256] @ X[256,128tile]; fused epilogues --
// by==0: theta (+bias) -> g_theta
// by==1: e = exp(pi+bias) -> g_pi, deterministic partial row sums -> g_psum
// by==2: per-pixel softmax over 128 channels -> out_dist
__global__ __launch_bounds__(256, 2) void k_feats(
    const float* __restrict__ content, const float* __restrict__ style,
    const float* __restrict__ w_theta, const float* __restrict__ b_theta,
    const float* __restrict__ w_pi,    const float* __restrict__ b_pi,
    const float* __restrict__ w_g,     const float* __restrict__ b_g,
    float* __restrict__ out_dist)
{
    uint32_t* As = (uint32_t*)dynsm;           // 128 x ASTR
    uint32_t* Bs = As + 128 * ASTR;            // 32 x BSTR
    float* Cs = dynsm;                         // overlay, 128 x CSTR
    __shared__ float sbias[128];
    __shared__ float red[256];
    __shared__ float cinvs[128];

    const int tid = threadIdx.x;
    const int lane = tid & 31, wid = tid >> 5;
    const int g = lane >> 2, t = lane & 3;
    const int wm = wid >> 1, wn = wid & 1;
    const int by = blockIdx.x;
    const int j0 = blockIdx.y * 128;
    const int kb = (j0 >= HP);
    const float* X = kb ? style : content;
    const int p0 = j0 - (kb ? HP : 0);
    const float* W  = (by == 0) ? w_theta : ((by == 1) ? w_pi : w_g);
    const float* Bv = (by == 0) ? b_theta : ((by == 1) ? b_pi : b_g);

    if (tid < 128) sbias[tid] = Bv[tid];

    float acc[2][8][4];
    #pragma unroll
    for (int mt = 0; mt < 2; mt++)
        #pragma unroll
        for (int nt = 0; nt < 8; nt++)
            #pragma unroll
            for (int q = 0; q < 4; q++) acc[mt][nt][q] = 0.f;

    for (int c0 = 0; c0 < CI; c0 += 32) {
        #pragma unroll
        for (int r = 0; r < 4; r++) {
            int lin = tid + r * 256;
            int m = lin >> 3, k4 = (lin & 7) << 2;
            float4 v = *(const float4*)(W + m * CI + c0 + k4);
            *(uint4*)(As + m * ASTR + k4) = f2tf4(v);
        }
        #pragma unroll
        for (int r = 0; r < 4; r++) {
            int lin = tid + r * 256;
            int k = lin >> 5, n4 = (lin & 31) << 2;
            float4 v = *(const float4*)(X + (size_t)(c0 + k) * HP + p0 + n4);
            *(uint4*)(Bs + k * BSTR + n4) = f2tf4(v);
        }
        __syncthreads();
        #pragma unroll
        for (int k8 = 0; k8 < 4; k8++) {
            int kk = k8 * 8;
            uint32_t af[2][4];
            #pragma unroll
            for (int mt = 0; mt < 2; mt++) {
                int r0 = wm * 32 + mt * 16 + g;
                af[mt][0] = As[r0 * ASTR + kk + t];
                af[mt][1] = As[(r0 + 8) * ASTR + kk + t];
                af[mt][2] = As[r0 * ASTR + kk + t + 4];
                af[mt][3] = As[(r0 + 8) * ASTR + kk + t + 4];
            }
            #pragma unroll
            for (int nt = 0; nt < 8; nt++) {
                uint32_t bf[2];
                int cb = wn * 64 + nt * 8 + g;
                bf[0] = Bs[(kk + t) * BSTR + cb];
                bf[1] = Bs[(kk + t + 4) * BSTR + cb];
                mma8(acc[0][nt], af[0], bf);
                mma8(acc[1][nt], af[1], bf);
            }
        }
        __syncthreads();
    }

    // stage C to smem (overlays As/Bs — safe after final syncthreads)
    #pragma unroll
    for (int mt = 0; mt < 2; mt++) {
        int r0 = wm * 32 + mt * 16 + g;
        #pragma unroll
        for (int nt = 0; nt < 8; nt++) {
            int c = wn * 64 + nt * 8 + 2 * t;
            *(float2*)(Cs + r0 * CSTR + c)       = make_float2(acc[mt][nt][0], acc[mt][nt][1]);
            *(float2*)(Cs + (r0 + 8) * CSTR + c) = make_float2(acc[mt][nt][2], acc[mt][nt][3]);
        }
    }
    __syncthreads();

    if (by == 0) {
        int row = tid >> 1, cb = (tid & 1) * 64;
        float b = sbias[row];
        float* dst = g_theta + (size_t)row * JJ + j0 + cb;
        #pragma unroll
        for (int q = 0; q < 64; q += 4) {
            float4 v = *(float4*)(Cs + row * CSTR + cb + q);
            v.x += b; v.y += b; v.z += b; v.w += b;
            *(float4*)(dst + q) = v;
        }
    } else if (by == 1) {
        int row = tid >> 1, cb = (tid & 1) * 64;
        float b = sbias[row];
        float* dst = g_pi + (size_t)row * JJ + j0 + cb;
        float s = 0.f;
        #pragma unroll
        for (int q = 0; q < 64; q += 4) {
            float4 v = *(float4*)(Cs + row * CSTR + cb + q);
            v.x = __expf(v.x + b); v.y = __expf(v.y + b);
            v.z = __expf(v.z + b); v.w = __expf(v.w + b);
            s += v.x + v.y + v.z + v.w;
            *(float4*)(dst + q) = v;
        }
        red[tid] = s;
        __syncthreads();
        if (tid < 128)
            g_psum[(size_t)tid * NJB + blockIdx.y] = red[2 * tid] + red[2 * tid + 1];
    } else {
        // per-pixel (column) softmax over 128 channels
        int col = tid >> 1, rb = (tid & 1) * 64;
        float m = -1e30f;
        #pragma unroll
        for (int i = 0; i < 64; i++)
            m = fmaxf(m, Cs[(rb + i) * CSTR + col] + sbias[rb + i]);
        red[tid] = m;
        __syncthreads();
        float cm = fmaxf(red[2 * col], red[2 * col + 1]);
        float s = 0.f;
        #pragma unroll
        for (int i = 0; i < 64; i++) {
            float e = __expf(Cs[(rb + i) * CSTR + col] + sbias[rb + i] - cm);
            Cs[(rb + i) * CSTR + col] = e;
            s += e;
        }
        __syncthreads();
        red[tid] = s;
        __syncthreads();
        if ((tid & 1) == 0) cinvs[col] = 1.f / (red[2 * col] + red[2 * col + 1]);
        __syncthreads();
        int row = tid >> 1, cb = (tid & 1) * 64;
        float* dst = out_dist + (size_t)row * JJ + j0 + cb;
        #pragma unroll
        for (int q = 0; q < 64; q += 4) {
            float4 v = *(float4*)(Cs + row * CSTR + cb + q);
            float4 iv = *(float4*)(cinvs + cb + q);
            v.x *= iv.x; v.y *= iv.y; v.z *= iv.z; v.w *= iv.w;
            *(float4*)(dst + q) = v;
        }
    }
}

// ---------------- K2: rowsum reduce (+ zero gun) ----------------------------
__global__ void k_rowsum()
{
    __shared__ float red[256];
    const int c = blockIdx.x;
    float s = 0.f;
    for (int i = threadIdx.x; i < NJB; i += 256) s += g_psum[c * NJB + i];
    red[threadIdx.x] = s;
    __syncthreads();
    for (int st = 128; st > 0; st >>= 1) {
        if (threadIdx.x < st) red[threadIdx.x] += red[threadIdx.x + st];
        __syncthreads();
    }
    if (threadIdx.x == 0) g_rinv[c] = 1.0f / red[0];
    if (threadIdx.x < 128) g_gun[c * 128 + threadIdx.x] = 0.f;
}

// ---------------- K3: gun[m][n] += sum_j theta[m][j]*e[n][j] (split-K, tf32)
__global__ __launch_bounds__(256, 2) void k_gun()
{
    __shared__ uint32_t At[128 * ASTR];
    __shared__ uint32_t Et[128 * ASTR];
    const int tid = threadIdx.x;
    const int lane = tid & 31, wid = tid >> 5;
    const int g = lane >> 2, t = lane & 3;
    const int wm = wid >> 1, wn = wid & 1;
    const size_t jb = (size_t)blockIdx.x * 1024;

    float acc[2][8][4];
    #pragma unroll
    for (int mt = 0; mt < 2; mt++)
        #pragma unroll
        for (int nt = 0; nt < 8; nt++)
            #pragma unroll
            for (int q = 0; q < 4; q++) acc[mt][nt][q] = 0.f;

    for (int jc = 0; jc < 1024; jc += 32) {
        size_t j0 = jb + jc;
        #pragma unroll
        for (int r = 0; r < 4; r++) {
            int lin = tid + r * 256;
            int m = lin >> 3, k4 = (lin & 7) << 2;
            float4 va = *(const float4*)(g_theta + (size_t)m * JJ + j0 + k4);
            *(uint4*)(At + m * ASTR + k4) = f2tf4(va);
            float4 vb = *(const float4*)(g_pi + (size_t)m * JJ + j0 + k4);
            *(uint4*)(Et + m * ASTR + k4) = f2tf4(vb);
        }
        __syncthreads();
        #pragma unroll
        for (int k8 = 0; k8 < 4; k8++) {
            int kk = k8 * 8;
            uint32_t af[2][4];
            #pragma unroll
            for (int mt = 0; mt < 2; mt++) {
                int r0 = wm * 32 + mt * 16 + g;
                af[mt][0] = At[r0 * ASTR + kk + t];
                af[mt][1] = At[(r0 + 8) * ASTR + kk + t];
                af[mt][2] = At[r0 * ASTR + kk + t + 4];
                af[mt][3] = At[(r0 + 8) * ASTR + kk + t + 4];
            }
            #pragma unroll
            for (int nt = 0; nt < 8; nt++) {
                uint32_t bf[2];
                int n0 = wn * 64 + nt * 8 + g;
                bf[0] = Et[n0 * ASTR + kk + t];
                bf[1] = Et[n0 * ASTR + kk + t + 4];
                mma8(acc[0][nt], af[0], bf);
                mma8(acc[1][nt], af[1], bf);
            }
        }
        __syncthreads();
    }
    #pragma unroll
    for (int mt = 0; mt < 2; mt++) {
        int r0 = wm * 32 + mt * 16 + g;
        #pragma unroll
        for (int nt = 0; nt < 8; nt++) {
            int c = wn * 64 + nt * 8 + 2 * t;
            atomicAdd(&g_gun[r0 * 128 + c],           acc[mt][nt][0]);
            atomicAdd(&g_gun[r0 * 128 + c + 1],       acc[mt][nt][1]);
            atomicAdd(&g_gun[(r0 + 8) * 128 + c],     acc[mt][nt][2]);
            atomicAdd(&g_gun[(r0 + 8) * 128 + c + 1], acc[mt][nt][3]);
        }
    }
}

// ---------------- K4: W2 = (w_out @ gun) * rinv[n] --------------------------
__global__ void k_w2(const float* __restrict__ w_out)
{
    const int o = blockIdx.x;
    const int n = threadIdx.x;
    float s = 0.f;
    #pragma unroll 8
    for (int m = 0; m < CA; m++) s += w_out[o * CA + m] * g_gun[m * 128 + n];
    g_w2[o * CA + n] = s * g_rinv[n];
}

// ---------------- K5: alpha_gathering = transpose(e * rinv) -----------------
__global__ __launch_bounds__(256) void k_gath(float* __restrict__ out_gath)
{
    __shared__ float tile[32][33];
    const int jt = blockIdx.x * 32, ct = blockIdx.y * 32;
    const int tx = threadIdx.x & 31, ty = threadIdx.x >> 5;
    #pragma unroll
    for (int r = 0; r < 4; r++) {
        int c = ct + ty + r * 8;
        tile[ty + r * 8][tx] = g_pi[(size_t)c * JJ + jt + tx] * g_rinv[c];
    }
    __syncthreads();
    #pragma unroll
    for (int r = 0; r < 4; r++) {
        int jl = ty + r * 8;
        out_gath[(size_t)(jt + jl) * CA + ct + tx] = tile[tx][jl];
    }
}

// ---------------- K6: out = W2[256,128] @ dist[128,J] + b_out (tf32) --------
__global__ __launch_bounds__(256, 2) void k_out(
    const float* __restrict__ b_out, const float* __restrict__ sg,
    float* __restrict__ out)
{
    uint32_t* As = (uint32_t*)dynsm;
    uint32_t* Bs = As + 128 * ASTR;
    float* Cs = dynsm;
    __shared__ float sbias[128];

    const int tid = threadIdx.x;
    const int lane = tid & 31, wid = tid >> 5;
    const int g = lane >> 2, t = lane & 3;
    const int wm = wid >> 1, wn = wid & 1;
    const int rb = blockIdx.x;             // 0..1 (output row half)
    const int j0 = blockIdx.y * 128;

    if (tid < 128) sbias[tid] = b_out[rb * 128 + tid];

    float acc[2][8][4];
    #pragma unroll
    for (int mt = 0; mt < 2; mt++)
        #pragma unroll
        for (int nt = 0; nt < 8; nt++)
            #pragma unroll
            for (int q = 0; q < 4; q++) acc[mt][nt][q] = 0.f;

    for (int c0 = 0; c0 < CA; c0 += 32) {
        #pragma unroll
        for (int r = 0; r < 4; r++) {
            int lin = tid + r * 256;
            int m = lin >> 3, k4 = (lin & 7) << 2;
            float4 v = *(const float4*)(g_w2 + (rb * 128 + m) * CA + c0 + k4);
            *(uint4*)(As + m * ASTR + k4) = f2tf4(v);
        }
        #pragma unroll
        for (int r = 0; r < 4; r++) {
            int lin = tid + r * 256;
            int k = lin >> 5, n4 = (lin & 31) << 2;
            float4 v = *(const float4*)(sg + (size_t)(c0 + k) * JJ + j0 + n4);
            *(uint4*)(Bs + k * BSTR + n4) = f2tf4(v);
        }
        __syncthreads();
        #pragma unroll
        for (int k8 = 0; k8 < 4; k8++) {
            int kk = k8 * 8;
            uint32_t af[2][4];
            #pragma unroll
            for (int mt = 0; mt < 2; mt++) {
                int r0 = wm * 32 + mt * 16 + g;
                af[mt][0] = As[r0 * ASTR + kk + t];
                af[mt][1] = As[(r0 + 8) * ASTR + kk + t];
                af[mt][2] = As[r0 * ASTR + kk + t + 4];
                af[mt][3] = As[(r0 + 8) * ASTR + kk + t + 4];
            }
            #pragma unroll
            for (int nt = 0; nt < 8; nt++) {
                uint32_t bf[2];
                int cb = wn * 64 + nt * 8 + g;
                bf[0] = Bs[(kk + t) * BSTR + cb];
                bf[1] = Bs[(kk + t + 4) * BSTR + cb];
                mma8(acc[0][nt], af[0], bf);
                mma8(acc[1][nt], af[1], bf);
            }
        }
        __syncthreads();
    }

    #pragma unroll
    for (int mt = 0; mt < 2; mt++) {
        int r0 = wm * 32 + mt * 16 + g;
        #pragma unroll
        for (int nt = 0; nt < 8; nt++) {
            int c = wn * 64 + nt * 8 + 2 * t;
            *(float2*)(Cs + r0 * CSTR + c)       = make_float2(acc[mt][nt][0], acc[mt][nt][1]);
            *(float2*)(Cs + (r0 + 8) * CSTR + c) = make_float2(acc[mt][nt][2], acc[mt][nt][3]);
        }
    }
    __syncthreads();

    const int kb = (j0 >= HP);
    const int p0 = j0 - (kb ? HP : 0);
    int row = tid >> 1, cb = (tid & 1) * 64;
    float b = sbias[row];
    float* dst = out + (kb ? (size_t)CI * HP : 0)
                 + (size_t)(rb * 128 + row) * HP + p0 + cb;
    #pragma unroll
    for (int q = 0; q < 64; q += 4) {
        float4 v = *(float4*)(Cs + row * CSTR + cb + q);
        v.x += b; v.y += b; v.z += b; v.w += b;
        *(float4*)(dst + q) = v;
    }
}

// ---------------- launch -----------------------------------------------------
extern "C" void kernel_launch(void* const* d_in, const int* in_sizes, int n_in,
                              void* d_out, int out_size)
{
    const float* content = (const float*)d_in[0];
    const float* style   = (const float*)d_in[1];
    const float* w_theta = (const float*)d_in[2];
    const float* b_theta = (const float*)d_in[3];
    const float* w_pi    = (const float*)d_in[4];
    const float* b_pi    = (const float*)d_in[5];
    const float* w_g     = (const float*)d_in[6];
    const float* b_g     = (const float*)d_in[7];
    const float* w_out   = (const float*)d_in[8];
    const float* b_out   = (const float*)d_in[9];

    float* out  = (float*)d_out;
    float* gath = out + (size_t)2 * CI * HP;            // alpha_gathering
    float* dist = gath + (size_t)CA * JJ;               // alpha_distribute

    const int DSM = 128 * CSTR * 4;                     // 67584 bytes
    cudaFuncSetAttribute(k_feats, cudaFuncAttributeMaxDynamicSharedMemorySize, DSM);
    cudaFuncSetAttribute(k_out,   cudaFuncAttributeMaxDynamicSharedMemorySize, DSM);

    k_feats<<<dim3(3, NJB), 256, DSM>>>(content, style, w_theta, b_theta,
                                        w_pi, b_pi, w_g, b_g, dist);
    k_rowsum<<<128, 256>>>();
    k_gun<<<128, 256>>>();
    k_w2<<<256, 128>>>(w_out);
    k_gath<<<dim3(JJ / 32, CA / 32), 256>>>(gath);
    k_out<<<dim3(2, NJB), 256, DSM>>>(b_out, dist, out);
}